// round 8
// baseline (speedup 1.0000x reference)
#include <cuda_runtime.h>
#include <math.h>

#define NN   2048
#define CC   64
#define NT   256            // threads per block
#define JPT  2              // j's per thread (packed f32x2)
#define JB   (NT * JPT)     // 512 j columns per block
#define GX   (NN / JB)      // 4
#define ICH  16             // i rows per block
#define GY   (NN / ICH)     // 128
#define NBLK (GX * GY)      // 512
#define NBUCK 64
#define L2E  1.4426950408889634f

typedef unsigned long long ull;

// ---- device scratch (zero-init at load; counters reset by last block) ----
__device__ float4     g_pos[NN];    // x, y, z, s0           (j-side)
__device__ float4     g_jexp[NN];   // eR_lo, eD_lo, w0, 0   (j-side)
__device__ ulonglong2 g_pA[NN];     // pack(-x,-x), pack(-y,-y)      (i-side)
__device__ ulonglong2 g_pB[NN];     // pack(-z,-z), pack(-s0,-s0)
__device__ ulonglong2 g_pC[NN];     // pack(eRhi,eRhi), pack(eDhi,eDhi)
__device__ ull        g_pW[NN];     // pack(w0,w0)
__device__ double     g_accs[NBUCK];
__device__ unsigned   g_count;

__device__ __forceinline__ float sqrt_approx(float x) {
    float r; asm("sqrt.approx.f32 %0, %1;" : "=f"(r) : "f"(x)); return r;
}
__device__ __forceinline__ float rcp_approx(float x) {
    float r; asm("rcp.approx.f32 %0, %1;" : "=f"(r) : "f"(x)); return r;
}
__device__ __forceinline__ float ex2_approx(float x) {
    float r; asm("ex2.approx.f32 %0, %1;" : "=f"(r) : "f"(x)); return r;
}
__device__ __forceinline__ ull pack2(float lo, float hi) {
    ull r; asm("mov.b64 %0, {%1, %2};" : "=l"(r) : "f"(lo), "f"(hi)); return r;
}
__device__ __forceinline__ void unpack2(float& lo, float& hi, ull v) {
    asm("mov.b64 {%0, %1}, %2;" : "=f"(lo), "=f"(hi) : "l"(v));
}
__device__ __forceinline__ ull add2(ull a, ull b) {
    ull r; asm("add.rn.f32x2 %0, %1, %2;" : "=l"(r) : "l"(a), "l"(b)); return r;
}
__device__ __forceinline__ ull mul2(ull a, ull b) {
    ull r; asm("mul.rn.f32x2 %0, %1, %2;" : "=l"(r) : "l"(a), "l"(b)); return r;
}
__device__ __forceinline__ ull fma2(ull a, ull b, ull c) {
    ull r; asm("fma.rn.f32x2 %0, %1, %2, %3;" : "=l"(r) : "l"(a), "l"(b), "l"(c)); return r;
}

// ---- per-node precompute, warp-cooperative: 1 warp per node ----
__global__ void __launch_bounds__(256) pre_kernel(
    const float* __restrict__ X,
    const float* __restrict__ embs,
    const float* __restrict__ w0,
    const float* __restrict__ s0,
    const float* __restrict__ df,
    const float* __restrict__ rf)
{
    const int lane = threadIdx.x & 31;
    const int n    = (blockIdx.x * 256 + threadIdx.x) >> 5;

    const float e0 = embs[(size_t)n * CC + lane];
    const float e1 = embs[(size_t)n * CC + 32 + lane];

    float rl = fmaf(e0, __ldg(rf + lane),      e1 * __ldg(rf + 32 + lane));
    float rh = fmaf(e0, __ldg(rf + 64 + lane), e1 * __ldg(rf + 96 + lane));
    float dl = fmaf(e0, __ldg(df + lane),      e1 * __ldg(df + 32 + lane));
    float dh = fmaf(e0, __ldg(df + 64 + lane), e1 * __ldg(df + 96 + lane));
#pragma unroll
    for (int off = 16; off > 0; off >>= 1) {
        rl += __shfl_xor_sync(0xFFFFFFFFu, rl, off);
        rh += __shfl_xor_sync(0xFFFFFFFFu, rh, off);
        dl += __shfl_xor_sync(0xFFFFFFFFu, dl, off);
        dh += __shfl_xor_sync(0xFFFFFFFFu, dh, off);
    }
    if (lane == 0) {
        const float w  = w0[n];
        const float x  = X[3*n], y = X[3*n+1], z = X[3*n+2], s = s0[n];
        const float eRh = ex2_approx(-L2E * rh);
        const float eDh = ex2_approx(-L2E * dh);
        g_pos[n]  = make_float4(x, y, z, s);
        g_jexp[n] = make_float4(ex2_approx(-L2E * rl), ex2_approx(-L2E * dl), w, 0.f);
        // i-side: duplicated/negated packed forms for zero-cost broadcast
        g_pA[n] = make_ulonglong2(pack2(-x, -x), pack2(-y, -y));
        g_pB[n] = make_ulonglong2(pack2(-z, -z), pack2(-s, -s));
        g_pC[n] = make_ulonglong2(pack2(eRh, eRh), pack2(eDh, eDh));
        g_pW[n] = pack2(w, w);
    }
}

// ---- pairwise energy: 2 packed j's per thread, 16 i's per block ----
__global__ void __launch_bounds__(NT, 4) pair_kernel(
    const float* __restrict__ mask, float* __restrict__ out)
{
    const int tid  = threadIdx.x;
    const int lane = tid & 31;
    const int wid  = tid >> 5;
    const int j0   = blockIdx.x * JB + tid * JPT;
    const int i0   = blockIdx.y * ICH;

    __shared__ ulonglong2 sA[ICH];   // (-x,-x), (-y,-y)
    __shared__ ulonglong2 sB[ICH];   // (-z,-z), (-s0,-s0)
    __shared__ ulonglong2 sC[ICH];   // (eRhi,eRhi), (eDhi,eDhi)
    __shared__ ull        sW[ICH];   // (w0,w0)

    // prefetch first group of 8 packed mask values
    float2 mk[8];
#pragma unroll
    for (int k = 0; k < 8; k++)
        mk[k] = __ldg((const float2*)(mask + (size_t)(i0 + k) * NN + j0));

    // stage i-side packed data
    if (tid < ICH) {
        sA[tid] = g_pA[i0 + tid];
        sB[tid] = g_pB[i0 + tid];
        sC[tid] = g_pC[i0 + tid];
        sW[tid] = g_pW[i0 + tid];
    }

    // j-side packed data (2 nodes)
    const float4 pjA = g_pos[j0],  pjB = g_pos[j0 + 1];
    const float4 ejA = g_jexp[j0], ejB = g_jexp[j0 + 1];
    const ull pjx2  = pack2(pjA.x, pjB.x);
    const ull pjy2  = pack2(pjA.y, pjB.y);
    const ull pjz2  = pack2(pjA.z, pjB.z);
    const ull ns0j2 = pack2(-pjA.w, -pjB.w);
    const ull ejR2  = pack2(ejA.x, ejB.x);
    const ull ejD2  = pack2(ejA.y, ejB.y);
    const ull w0j2  = pack2(ejA.z, ejB.z);

    // packed constants
    const ull one2  = pack2(1.f, 1.f);
    const ull eps2  = pack2(3e-6f, 3e-6f);
    const ull c08   = pack2(0.8f, 0.8f);
    const ull c04   = pack2(0.4f, 0.4f);
    const ull cNL2E = pack2(-L2E, -L2E);
    const ull c06L  = pack2(0.6f * L2E, 0.6f * L2E);
    const ull c009L = pack2(-0.09f * L2E, -0.09f * L2E);
    const ull cN115 = pack2(-1.f/15.f, -1.f/15.f);   // -(1/3)/5
    const ull cN130 = pack2(-1.f/30.f, -1.f/30.f);   // -(1/6)/5
    const ull cWeps = pack2(1e-6f, 1e-6f);
    const ull cRepl = pack2(-0.3f * L2E, -0.3f * L2E);

    __syncthreads();

    ull acc2 = pack2(0.f, 0.f);
#pragma unroll
    for (int g = 0; g < 2; g++) {
#pragma unroll
        for (int k = 0; k < 8; k++) {
            const int kk = g * 8 + k;
            const ulonglong2 ia = sA[kk];
            const ulonglong2 ib = sB[kk];
            const ulonglong2 ic = sC[kk];
            const ull        iw = sW[kk];

            // r2 = dx^2 + dy^2 + dz^2 + 3e-6  (packed)
            const ull dx2 = add2(pjx2, ia.x);
            const ull dy2 = add2(pjy2, ia.y);
            const ull dz2 = add2(pjz2, ib.x);
            const ull r22 = fma2(dx2, dx2, fma2(dy2, dy2, fma2(dz2, dz2, eps2)));

            float ra, rb; unpack2(ra, rb, r22);
            const ull D2 = pack2(sqrt_approx(ra), sqrt_approx(rb));

            // sigmoids: 1/(1 + e_i * e_j)
            const ull fr2 = fma2(ic.x, ejR2, one2);
            const ull fd2 = fma2(ic.y, ejD2, one2);
            float fra, frb, fda, fdb;
            unpack2(fra, frb, fr2); unpack2(fda, fdb, fd2);
            const ull sr2 = pack2(rcp_approx(fra), rcp_approx(frb));
            const ull sd2 = pack2(rcp_approx(fda), rcp_approx(fdb));

            // Dm = D - (s0i + s0j) * (0.8*sr + 0.4)
            const ull kf2  = fma2(c08, sr2, c04);
            const ull npw2 = add2(ib.y, ns0j2);           // -(s0i+s0j)
            const ull Dm2  = fma2(npw2, kf2, D2);

            // t = exp(-Dm^2), u = exp(0.6 Dm - 0.09)
            const ull dmsq2 = mul2(Dm2, Dm2);
            const ull targ2 = mul2(dmsq2, cNL2E);
            const ull uarg2 = fma2(c06L, Dm2, c009L);
            float ta, tb, ua, ub;
            unpack2(ta, tb, targ2); unpack2(ua, ub, uarg2);
            const ull t2 = pack2(ex2_approx(ta), ex2_approx(tb));
            const ull u2 = pack2(ex2_approx(ua), ex2_approx(ub));

            // attr3 = t*u + t^3 + t^10
            const ull tsq2 = mul2(t2, t2);
            const ull t3_2 = mul2(tsq2, t2);
            const ull t4_2 = mul2(tsq2, tsq2);
            const ull t10_2 = mul2(mul2(t4_2, t4_2), tsq2);
            const ull attr2 = fma2(t2, u2, add2(t3_2, t10_2));

            // -w/5 = -sqrt(w0i*w0j + 1e-6) * (sd/15 + 1/30)
            const ull sd3n2 = fma2(sd2, cN115, cN130);
            const ull warg2 = fma2(iw, w0j2, cWeps);
            float wa, wb; unpack2(wa, wb, warg2);
            const ull sw2 = pack2(sqrt_approx(wa), sqrt_approx(wb));
            const ull wn2 = mul2(sw2, sd3n2);

            // repl/5 = exp(-0.3 * D * r2)
            const ull rarg2 = mul2(mul2(D2, r22), cRepl);
            float ea, eb; unpack2(ea, eb, rarg2);
            const ull e2 = pack2(ex2_approx(ea), ex2_approx(eb));

            // acc += m * (repl/5 - (w/5)*attr3)      [final x5 at the end]
            const ull term2 = fma2(wn2, attr2, e2);
            const ull m2 = pack2(mk[k].x, mk[k].y);
            acc2 = fma2(m2, term2, acc2);
        }
        if (g == 0) {
#pragma unroll
            for (int k = 0; k < 8; k++)
                mk[k] = __ldg((const float2*)(mask + (size_t)(i0 + 8 + k) * NN + j0));
        }
    }

    float aLo, aHi; unpack2(aLo, aHi, acc2);
    float acc = 5.f * (aLo + aHi);

    // ---- warp reduction + per-warp bucket atomic ----
#pragma unroll
    for (int off = 16; off > 0; off >>= 1)
        acc += __shfl_down_sync(0xFFFFFFFFu, acc, off);

    if (lane == 0) {
        const int bucket = ((blockIdx.y * GX + blockIdx.x) * 8 + wid) & (NBUCK - 1);
        atomicAdd(&g_accs[bucket], (double)acc);
    }
    __syncthreads();

    if (tid == 0) {
        __threadfence();
        const unsigned prev = atomicAdd(&g_count, 1u);
        if (prev == NBLK - 1) {
            __threadfence();
            double total = 0.0;
#pragma unroll
            for (int b = 0; b < NBUCK; b++) {
                total += g_accs[b];
                g_accs[b] = 0.0;     // reset for next graph replay
            }
            const float r = (float)total;
            out[0] = isnan(r) ? 1e-6f : r;
            g_count = 0u;
        }
    }
}

extern "C" void kernel_launch(void* const* d_in, const int* in_sizes, int n_in,
                              void* d_out, int out_size) {
    const float* X    = (const float*)d_in[0];
    const float* embs = (const float*)d_in[1];
    const float* w0   = (const float*)d_in[2];
    const float* s0   = (const float*)d_in[3];
    const float* mask = (const float*)d_in[4];
    const float* df   = (const float*)d_in[5];
    const float* rf   = (const float*)d_in[6];
    float* out = (float*)d_out;

    pre_kernel<<<NN / 8, 256>>>(X, embs, w0, s0, df, rf);
    dim3 grid(GX, GY);   // 4 x 128 = 512 blocks, single wave at 4 blocks/SM
    pair_kernel<<<grid, NT>>>(mask, out);
}

// round 9
// speedup vs baseline: 1.1201x; 1.1201x over previous
#include <cuda_runtime.h>
#include <math.h>

#define NN   2048
#define CC   64
#define NT   256            // threads per block
#define JPT  2              // j's per thread (independent scalar chains)
#define JB   (NT * JPT)     // 512 j columns per block
#define GX   (NN / JB)      // 4
#define ICH  16             // i rows per block
#define GY   (NN / ICH)     // 128
#define NBLK (GX * GY)      // 512
#define NBUCK 64
#define L2E  1.4426950408889634f

// ---- device scratch (zero-init at load; counters reset by last block) ----
__device__ float4   g_pos[NN];   // x, y, z, |p|^2
__device__ float4   g_jn[NN];    // eR_lo, eD_lo, -s0, sqrt(w0)   (j-side)
__device__ float4   g_in[NN];    // eR_hi, eD_hi, -s0, sqrt(w0)   (i-side)
__device__ double   g_accs[NBUCK];
__device__ unsigned g_count;

__device__ __forceinline__ float sqrt_approx(float x) {
    float r; asm("sqrt.approx.f32 %0, %1;" : "=f"(r) : "f"(x)); return r;
}
__device__ __forceinline__ float rcp_approx(float x) {
    float r; asm("rcp.approx.f32 %0, %1;" : "=f"(r) : "f"(x)); return r;
}
__device__ __forceinline__ float ex2_approx(float x) {
    float r; asm("ex2.approx.f32 %0, %1;" : "=f"(r) : "f"(x)); return r;
}

// ---- per-node precompute, warp-cooperative: 1 warp per node ----
__global__ void __launch_bounds__(256) pre_kernel(
    const float* __restrict__ X,
    const float* __restrict__ embs,
    const float* __restrict__ w0,
    const float* __restrict__ s0,
    const float* __restrict__ df,
    const float* __restrict__ rf)
{
    const int lane = threadIdx.x & 31;
    const int n    = (blockIdx.x * 256 + threadIdx.x) >> 5;

    const float e0 = embs[(size_t)n * CC + lane];
    const float e1 = embs[(size_t)n * CC + 32 + lane];

    float rl = fmaf(e0, __ldg(rf + lane),      e1 * __ldg(rf + 32 + lane));
    float rh = fmaf(e0, __ldg(rf + 64 + lane), e1 * __ldg(rf + 96 + lane));
    float dl = fmaf(e0, __ldg(df + lane),      e1 * __ldg(df + 32 + lane));
    float dh = fmaf(e0, __ldg(df + 64 + lane), e1 * __ldg(df + 96 + lane));
#pragma unroll
    for (int off = 16; off > 0; off >>= 1) {
        rl += __shfl_xor_sync(0xFFFFFFFFu, rl, off);
        rh += __shfl_xor_sync(0xFFFFFFFFu, rh, off);
        dl += __shfl_xor_sync(0xFFFFFFFFu, dl, off);
        dh += __shfl_xor_sync(0xFFFFFFFFu, dh, off);
    }
    if (lane == 0) {
        const float x = X[3*n], y = X[3*n+1], z = X[3*n+2];
        const float q  = fmaf(x, x, fmaf(y, y, z * z));
        const float ns = -s0[n];
        const float sw = sqrtf(w0[n]);          // exact per-node sqrt
        g_pos[n] = make_float4(x, y, z, q);
        g_jn[n]  = make_float4(ex2_approx(-L2E * rl), ex2_approx(-L2E * dl), ns, sw);
        g_in[n]  = make_float4(ex2_approx(-L2E * rh), ex2_approx(-L2E * dh), ns, sw);
    }
}

// ---- one pair evaluation (scalar, minimal ops) ----
__device__ __forceinline__ float pair_term(
    const float4 i1,   // -2xi, -2yi, -2zi, qi
    const float4 i2,   // eRhi, eDhi, -s0i, sw0i
    float xj, float yj, float zj, float qje,   // qje = qj + 3e-6
    float eRj, float eDj, float ns0j, float swj)
{
    // r2 = qi + qj + 3e-6 - 2*dot(pi, pj)
    const float qsum = i1.w + qje;
    const float r2 = fmaf(i1.x, xj, fmaf(i1.y, yj, fmaf(i1.z, zj, qsum)));
    const float D  = sqrt_approx(r2);

    // sigmoids
    const float sr = rcp_approx(fmaf(i2.x, eRj, 1.f));
    const float sd = rcp_approx(fmaf(i2.y, eDj, 1.f));

    const float kf   = fmaf(0.8f, sr, 0.4f);
    const float nsum = i2.z + ns0j;              // -(s0i + s0j)
    const float Dm   = fmaf(nsum, kf, D);

    // t = exp(-Dm^2), u = exp(0.6 Dm - 0.09)
    const float targ = (Dm * (-L2E)) * Dm;
    const float t    = ex2_approx(targ);
    const float u    = ex2_approx(fmaf(0.6f * L2E, Dm, -0.09f * L2E));
    const float t2   = t * t;
    const float t3   = t2 * t;
    const float t4   = t2 * t2;
    const float t10  = (t4 * t4) * t2;
    const float attr3 = fmaf(t, u, t3 + t10);

    // -w/5 = -sw0i*sw0j*(sd/15 + 1/30)
    const float sd3n = fmaf(sd, -1.f/15.f, -1.f/30.f);
    const float wn   = (i2.w * swj) * sd3n;

    // repl/5 = exp(-0.3 * D * r2)
    const float e = ex2_approx((D * (-0.3f * L2E)) * r2);

    return fmaf(wn, attr3, e);
}

// ---- pairwise energy: 2 scalar j's per thread, 16 i's per block ----
__global__ void __launch_bounds__(NT, 4) pair_kernel(
    const float* __restrict__ mask, float* __restrict__ out)
{
    const int tid  = threadIdx.x;
    const int lane = tid & 31;
    const int wid  = tid >> 5;
    const int j0   = blockIdx.x * JB + tid * JPT;
    const int i0   = blockIdx.y * ICH;

    __shared__ float4 sI1[ICH];   // -2x, -2y, -2z, q
    __shared__ float4 sI2[ICH];   // eRhi, eDhi, -s0, sw0

    // stage i-side data
    if (tid < ICH) {
        const float4 p = g_pos[i0 + tid];
        sI1[tid] = make_float4(-2.f * p.x, -2.f * p.y, -2.f * p.z, p.w);
        sI2[tid] = g_in[i0 + tid];
    }

    // j-side data (2 nodes)
    const float4 pA = g_pos[j0],  pB = g_pos[j0 + 1];
    const float4 nA = g_jn[j0],   nB = g_jn[j0 + 1];
    const float qAe = pA.w + 3e-6f, qBe = pB.w + 3e-6f;

    // prefetch first group of 4 packed mask rows
    float2 mk[4], mkn[4];
#pragma unroll
    for (int k = 0; k < 4; k++)
        mk[k] = __ldg((const float2*)(mask + (size_t)(i0 + k) * NN + j0));

    __syncthreads();

    float accA = 0.f, accB = 0.f;
#pragma unroll
    for (int g = 0; g < ICH / 4; g++) {
        if (g + 1 < ICH / 4) {
#pragma unroll
            for (int k = 0; k < 4; k++)
                mkn[k] = __ldg((const float2*)(mask + (size_t)(i0 + (g+1)*4 + k) * NN + j0));
        }
#pragma unroll
        for (int k = 0; k < 4; k++) {
            const int kk = g * 4 + k;
            const float4 i1 = sI1[kk];
            const float4 i2 = sI2[kk];
            const float tA = pair_term(i1, i2, pA.x, pA.y, pA.z, qAe,
                                       nA.x, nA.y, nA.z, nA.w);
            const float tB = pair_term(i1, i2, pB.x, pB.y, pB.z, qBe,
                                       nB.x, nB.y, nB.z, nB.w);
            accA = fmaf(mk[k].x, tA, accA);
            accB = fmaf(mk[k].y, tB, accB);
        }
#pragma unroll
        for (int k = 0; k < 4; k++) mk[k] = mkn[k];
    }

    float acc = 5.f * (accA + accB);

    // ---- warp reduction + per-warp bucket atomic ----
#pragma unroll
    for (int off = 16; off > 0; off >>= 1)
        acc += __shfl_down_sync(0xFFFFFFFFu, acc, off);

    if (lane == 0) {
        const int bucket = ((blockIdx.y * GX + blockIdx.x) * 8 + wid) & (NBUCK - 1);
        atomicAdd(&g_accs[bucket], (double)acc);
    }
    __syncthreads();

    if (tid == 0) {
        __threadfence();
        const unsigned prev = atomicAdd(&g_count, 1u);
        if (prev == NBLK - 1) {
            __threadfence();
            double total = 0.0;
#pragma unroll
            for (int b = 0; b < NBUCK; b++) {
                total += g_accs[b];
                g_accs[b] = 0.0;     // reset for next graph replay
            }
            const float r = (float)total;
            out[0] = isnan(r) ? 1e-6f : r;
            g_count = 0u;
        }
    }
}

extern "C" void kernel_launch(void* const* d_in, const int* in_sizes, int n_in,
                              void* d_out, int out_size) {
    const float* X    = (const float*)d_in[0];
    const float* embs = (const float*)d_in[1];
    const float* w0   = (const float*)d_in[2];
    const float* s0   = (const float*)d_in[3];
    const float* mask = (const float*)d_in[4];
    const float* df   = (const float*)d_in[5];
    const float* rf   = (const float*)d_in[6];
    float* out = (float*)d_out;

    pre_kernel<<<NN / 8, 256>>>(X, embs, w0, s0, df, rf);
    dim3 grid(GX, GY);   // 4 x 128 = 512 blocks
    pair_kernel<<<grid, NT>>>(mask, out);
}